// round 16
// baseline (speedup 1.0000x reference)
#include <cuda_runtime.h>

#define BB 4096
#define TT 400
#define CC 42
#define HH 16
#define SCALE 2.885390081777927f  // 2*log2(e), folded into U, recurrent weights, bias1
#define NCH 25                    // 25 chunks x 16 timesteps = 400
#define PAIRS_PER_BLOCK 6
#define GRID_BLOCKS 342           // ceil(2048 / 6), tail pairs clamped

typedef unsigned long long u64;

// named barriers: full[q]=1+q (producer arrives, consumers sync), q=0..1
//                 empty[q]=3+q (consumers arrive, producer syncs)
// max id 4 -> 5 HW barriers per block -> 3 blocks/SM fit the 16-barrier pool.
#define BAR_SYNC(id)   asm volatile("bar.sync %0, 128;" ::"r"(id) : "memory")
#define BAR_ARRIVE(id) asm volatile("bar.arrive %0, 128;" ::"r"(id) : "memory")

// ---------- f32x2 helpers ----------
__device__ __forceinline__ u64 pk2(float lo, float hi) {
    u64 r;
    asm("mov.b64 %0, {%1, %2};" : "=l"(r) : "f"(lo), "f"(hi));
    return r;
}
__device__ __forceinline__ void up2(u64 v, float& a, float& b) {
    asm("mov.b64 {%0, %1}, %2;" : "=f"(a), "=f"(b) : "l"(v));
}
__device__ __forceinline__ u64 fma2(u64 a, u64 b, u64 c) {
    u64 d;
    asm("fma.rn.f32x2 %0, %1, %2, %3;" : "=l"(d) : "l"(a), "l"(b), "l"(c));
    return d;
}
__device__ __forceinline__ u64 add2(u64 a, u64 b) {
    u64 d;
    asm("add.rn.f32x2 %0, %1, %2;" : "=l"(d) : "l"(a), "l"(b));
    return d;
}
// tanh with pre-scaled argument: z = 2*log2(e)*x  ->  tanh(x) = 1 - 2/(1+2^z)
__device__ __forceinline__ float tanh_pre(float z) {
    float e, r;
    asm("ex2.approx.f32 %0, %1;" : "=f"(e) : "f"(z));
    asm("rcp.approx.f32 %0, %1;" : "=f"(r) : "f"(e + 1.0f));
    return fmaf(-2.0f, r, 1.0f);
}
__device__ __forceinline__ u64 tanh2_pre(u64 z) {
    float a, b;
    up2(z, a, b);
    return pk2(tanh_pre(a), tanh_pre(b));
}

// ---------- Fused kernel: 3 consumer warps + 1 producer warp per block ----------
// Block = 6 pairs (12 batches), 128 threads. Warps 0-2 consumers (SMSP 0-2), warp 3
// producer (SMSP 3) — consumers stay segregated from producer bursts (empirical law
// from R8/R14/R15), at lower consumer density (3/SMSP on wall SMs vs 3.46).
__global__ void __launch_bounds__(128, 3) kFused(
    const float* __restrict__ x,
    const float* __restrict__ h0in,
    const float* __restrict__ Wih0, const float* __restrict__ Whh0,
    const float* __restrict__ bih0, const float* __restrict__ bhh0,
    const float* __restrict__ Wih1, const float* __restrict__ Whh1,
    const float* __restrict__ bih1, const float* __restrict__ bhh1,
    const float* __restrict__ Wfc, const float* __restrict__ bfc,
    float* __restrict__ out)
{
    __shared__ __align__(16) u64 sU[2][PAIRS_PER_BLOCK][16][17]; // [buf][ploc][i][t] padded
    __shared__ __align__(16) u64 swd[CC][HH];                    // producer weights (dup f32x2)
    __shared__ u64 sb2[HH];                                      // producer bias (dup f32x2)
    __shared__ __align__(16) ulonglong2 sh[3][2][17];            // exchange [rw][s][i]={h0,h1}

    int tid = threadIdx.x;
    int w = tid >> 5;
    int lane = tid & 31;
    int i = lane & 15;   // consumer: hidden unit; producer: t-slot
    int s = lane >> 4;   // pair slot

    // stage producer weights/bias (all threads help)
    for (int k = tid; k < CC * HH; k += 128) {
        int c = k >> 4, ii = k & 15;
        float wv = SCALE * Wih0[ii * CC + c];
        swd[c][ii] = pk2(wv, wv);
    }
    if (tid < HH) {
        float b = SCALE * (bih0[tid] + bhh0[tid]);
        sb2[tid] = pk2(b, b);
    }
    __syncthreads();

    const bool is_prod = (w == 3);

    if (is_prod) {
        // ============ producer: 3 passes per chunk (plocs {0,1},{2,3},{4,5}) ============
        for (int j = 0; j < NCH; j++) {
            if (j >= 2) BAR_SYNC(3 + (j & 1));  // consumers done with buf of chunk j-2
#pragma unroll
            for (int pass = 0; pass < 3; pass++) {
                int ploc = pass * 2 + s;
                int p = blockIdx.x * PAIRS_PER_BLOCK + ploc;
                if (p > 2047) p = 2047;  // tail clamp (duplicate work, identical values)
                const float* pa = x + (size_t)(2 * p) * (CC * TT) + i + j * 16;
                const float* pb = pa + CC * TT;
                u64 u[16];
#pragma unroll
                for (int ii = 0; ii < 16; ii++) u[ii] = sb2[ii];
#pragma unroll 6
                for (int c = 0; c < CC; c++) {
                    u64 xp = pk2(pa[c * TT], pb[c * TT]);
                    const ulonglong2* wp = (const ulonglong2*)&swd[c][0];
#pragma unroll
                    for (int k8 = 0; k8 < 8; k8++) {
                        ulonglong2 w2 = wp[k8];
                        u[2 * k8]     = fma2(w2.x, xp, u[2 * k8]);
                        u[2 * k8 + 1] = fma2(w2.y, xp, u[2 * k8 + 1]);
                    }
                }
                u64* dst = &sU[j & 1][ploc][0][i];
#pragma unroll
                for (int ii = 0; ii < 16; ii++) dst[ii * 17] = u[ii];
            }
            BAR_ARRIVE(1 + (j & 1));  // buf (chunk j) full
        }
        return;
    }

    // ================= consumer (R14 math; rw in 0..2, 6 plocs) =================
    int rw = w;                                   // 0..2
    int ploc = rw * 2 + s;                        // 0..5
    int p = blockIdx.x * PAIRS_PER_BLOCK + ploc;
    if (p > 2047) p = 2047;                       // tail clamp
    int b0 = 2 * p, b1 = b0 + 1;

    u64 WH0[16], WI1[16], WH1[16];
#pragma unroll
    for (int j = 0; j < 16; j++) {
        float v0 = SCALE * Whh0[i * 16 + j];
        float v1 = SCALE * Wih1[i * 16 + j];
        float v2 = SCALE * Whh1[i * 16 + j];
        WH0[j] = pk2(v0, v0);
        WI1[j] = pk2(v1, v1);
        WH1[j] = pk2(v2, v2);
    }
    float bf1 = SCALE * (bih1[i] + bhh1[i]);
    u64 B1S = pk2(bf1, bf1);
    u64 h1ini = pk2(h0in[BB * HH + b0 * 16 + i], h0in[BB * HH + b1 * 16 + i]);
    u64 h0i = pk2(h0in[b0 * 16 + i], h0in[b1 * 16 + i]);

    ulonglong2* myh = &sh[rw][s][i];
    const ulonglong2* hrd = &sh[rw][s][0];
    const u64* ubase = &sU[0][ploc][i][0];
    const int bufstride = PAIRS_PER_BLOCK * 16 * 17;  // u64 elements per buffer

    *myh = make_ulonglong2(h0i, h1ini);
    __syncwarp();

// one recurrence step: exchange holds {h0(m-1), h1(m-2)}; produces {h0(m), h1(m-1)}.
#define CSTEP(UVAL, OVRC)                                                          \
    {                                                                              \
        ulonglong2 qv;                                                             \
        u64 a0, a1, c0, c1, d0, d1;                                                \
        qv = hrd[0];  a0 = fma2(WH0[0], qv.x, (UVAL));                             \
                      c0 = fma2(WI1[0], qv.x, B1S);                                \
                      d0 = fma2(WH1[0], qv.y, 0ull);                               \
        qv = hrd[1];  a1 = fma2(WH0[1], qv.x, 0ull);                               \
                      c1 = fma2(WI1[1], qv.x, 0ull);                               \
                      d1 = fma2(WH1[1], qv.y, 0ull);                               \
        qv = hrd[2];  a0 = fma2(WH0[2], qv.x, a0);                                 \
                      c0 = fma2(WI1[2], qv.x, c0); d0 = fma2(WH1[2], qv.y, d0);    \
        qv = hrd[3];  a1 = fma2(WH0[3], qv.x, a1);                                 \
                      c1 = fma2(WI1[3], qv.x, c1); d1 = fma2(WH1[3], qv.y, d1);    \
        qv = hrd[4];  a0 = fma2(WH0[4], qv.x, a0);                                 \
                      c0 = fma2(WI1[4], qv.x, c0); d0 = fma2(WH1[4], qv.y, d0);    \
        qv = hrd[5];  a1 = fma2(WH0[5], qv.x, a1);                                 \
                      c1 = fma2(WI1[5], qv.x, c1); d1 = fma2(WH1[5], qv.y, d1);    \
        qv = hrd[6];  a0 = fma2(WH0[6], qv.x, a0);                                 \
                      c0 = fma2(WI1[6], qv.x, c0); d0 = fma2(WH1[6], qv.y, d0);    \
        qv = hrd[7];  a1 = fma2(WH0[7], qv.x, a1);                                 \
                      c1 = fma2(WI1[7], qv.x, c1); d1 = fma2(WH1[7], qv.y, d1);    \
        qv = hrd[8];  a0 = fma2(WH0[8], qv.x, a0);                                 \
                      c0 = fma2(WI1[8], qv.x, c0); d0 = fma2(WH1[8], qv.y, d0);    \
        qv = hrd[9];  a1 = fma2(WH0[9], qv.x, a1);                                 \
                      c1 = fma2(WI1[9], qv.x, c1); d1 = fma2(WH1[9], qv.y, d1);    \
        qv = hrd[10]; a0 = fma2(WH0[10], qv.x, a0);                                \
                      c0 = fma2(WI1[10], qv.x, c0); d0 = fma2(WH1[10], qv.y, d0);  \
        qv = hrd[11]; a1 = fma2(WH0[11], qv.x, a1);                                \
                      c1 = fma2(WI1[11], qv.x, c1); d1 = fma2(WH1[11], qv.y, d1);  \
        qv = hrd[12]; a0 = fma2(WH0[12], qv.x, a0);                                \
                      c0 = fma2(WI1[12], qv.x, c0); d0 = fma2(WH1[12], qv.y, d0);  \
        qv = hrd[13]; a1 = fma2(WH0[13], qv.x, a1);                                \
                      c1 = fma2(WI1[13], qv.x, c1); d1 = fma2(WH1[13], qv.y, d1);  \
        qv = hrd[14]; a0 = fma2(WH0[14], qv.x, a0);                                \
                      c0 = fma2(WI1[14], qv.x, c0); d0 = fma2(WH1[14], qv.y, d0);  \
        qv = hrd[15]; a1 = fma2(WH0[15], qv.x, a1);                                \
                      c1 = fma2(WI1[15], qv.x, c1); d1 = fma2(WH1[15], qv.y, d1);  \
        u64 h0n = tanh2_pre(add2(a0, a1));                                         \
        u64 h1n = tanh2_pre(add2(add2(c0, c1), add2(d0, d1)));                     \
        if (OVRC) h1n = h1ini;                                                     \
        *myh = make_ulonglong2(h0n, h1n);                                          \
    }

    for (int kk = 0; kk < NCH; kk++) {
        int q = kk & 1;
        BAR_SYNC(1 + q);  // wait: buf q holds chunk kk
        const u64* ur = ubase + q * bufstride;
        if (kk == 0) {
            {
                u64 uval = ur[0];
                CSTEP(uval, true);
            }
#pragma unroll
            for (int stp = 1; stp < 16; stp++) {
                u64 uval = ur[stp];
                CSTEP(uval, false);
            }
        } else {
#pragma unroll
            for (int stp = 0; stp < 16; stp++) {
                u64 uval = ur[stp];
                CSTEP(uval, false);
            }
        }
        BAR_ARRIVE(3 + q);  // buf q consumed
    }

    // exchange now holds {h0(399), h1(398)} — final step computes h1(399)
    {
        ulonglong2 qv;
        u64 c0, c1, d0, d1;
        qv = hrd[0];  c0 = fma2(WI1[0], qv.x, B1S);  d0 = fma2(WH1[0], qv.y, 0ull);
        qv = hrd[1];  c1 = fma2(WI1[1], qv.x, 0ull); d1 = fma2(WH1[1], qv.y, 0ull);
        qv = hrd[2];  c0 = fma2(WI1[2], qv.x, c0);   d0 = fma2(WH1[2], qv.y, d0);
        qv = hrd[3];  c1 = fma2(WI1[3], qv.x, c1);   d1 = fma2(WH1[3], qv.y, d1);
        qv = hrd[4];  c0 = fma2(WI1[4], qv.x, c0);   d0 = fma2(WH1[4], qv.y, d0);
        qv = hrd[5];  c1 = fma2(WI1[5], qv.x, c1);   d1 = fma2(WH1[5], qv.y, d1);
        qv = hrd[6];  c0 = fma2(WI1[6], qv.x, c0);   d0 = fma2(WH1[6], qv.y, d0);
        qv = hrd[7];  c1 = fma2(WI1[7], qv.x, c1);   d1 = fma2(WH1[7], qv.y, d1);
        qv = hrd[8];  c0 = fma2(WI1[8], qv.x, c0);   d0 = fma2(WH1[8], qv.y, d0);
        qv = hrd[9];  c1 = fma2(WI1[9], qv.x, c1);   d1 = fma2(WH1[9], qv.y, d1);
        qv = hrd[10]; c0 = fma2(WI1[10], qv.x, c0);  d0 = fma2(WH1[10], qv.y, d0);
        qv = hrd[11]; c1 = fma2(WI1[11], qv.x, c1);  d1 = fma2(WH1[11], qv.y, d1);
        qv = hrd[12]; c0 = fma2(WI1[12], qv.x, c0);  d0 = fma2(WH1[12], qv.y, d0);
        qv = hrd[13]; c1 = fma2(WI1[13], qv.x, c1);  d1 = fma2(WH1[13], qv.y, d1);
        qv = hrd[14]; c0 = fma2(WI1[14], qv.x, c0);  d0 = fma2(WH1[14], qv.y, d0);
        qv = hrd[15]; c1 = fma2(WI1[15], qv.x, c1);  d1 = fma2(WH1[15], qv.y, d1);
        u64 h1n = tanh2_pre(add2(add2(c0, c1), add2(d0, d1)));
        *myh = make_ulonglong2(0ull, h1n);
        __syncwarp();
    }
    // final FC (NC=2): out[b][c] = bfc[c] + sum_j Wfc[c][j] * h1(399)[j]
    if (i < 2) {
        float bfv = bfc[i];
        u64 acc = pk2(bfv, bfv);
#pragma unroll
        for (int j = 0; j < 16; j++) {
            float wv = Wfc[i * 16 + j];
            acc = fma2(pk2(wv, wv), hrd[j].y, acc);
        }
        float lo, hi;
        up2(acc, lo, hi);
        out[b0 * 2 + i] = lo;
        out[b1 * 2 + i] = hi;
    }
#undef CSTEP
}

extern "C" void kernel_launch(void* const* d_in, const int* in_sizes, int n_in,
                              void* d_out, int out_size) {
    const float* x    = (const float*)d_in[0];
    const float* h0   = (const float*)d_in[1];
    const float* Wih0 = (const float*)d_in[2];
    const float* Whh0 = (const float*)d_in[3];
    const float* bih0 = (const float*)d_in[4];
    const float* bhh0 = (const float*)d_in[5];
    const float* Wih1 = (const float*)d_in[6];
    const float* Whh1 = (const float*)d_in[7];
    const float* bih1 = (const float*)d_in[8];
    const float* bhh1 = (const float*)d_in[9];
    const float* Wfc  = (const float*)d_in[10];
    const float* bfc  = (const float*)d_in[11];
    float* out = (float*)d_out;

    kFused<<<GRID_BLOCKS, 128>>>(x, h0, Wih0, Whh0, bih0, bhh0,
                                 Wih1, Whh1, bih1, bhh1, Wfc, bfc, out);
}

// round 17
// speedup vs baseline: 2.2115x; 2.2115x over previous
#include <cuda_runtime.h>

#define BB 4096
#define TT 400
#define CC 42
#define HH 16
#define NCH 25                    // 25 chunks x 16 timesteps = 400

typedef unsigned long long u64;

// named barriers: full[q]=1+q (producers arrive, consumers sync), q=0..3
//                 empty[q]=5+q (consumers arrive, producers sync)
#define BAR_SYNC(id)   asm volatile("bar.sync %0, 128;" ::"r"(id) : "memory")
#define BAR_ARRIVE(id) asm volatile("bar.arrive %0, 128;" ::"r"(id) : "memory")

// ---------- f32x2 helpers ----------
__device__ __forceinline__ u64 pk2(float lo, float hi) {
    u64 r;
    asm("mov.b64 %0, {%1, %2};" : "=l"(r) : "f"(lo), "f"(hi));
    return r;
}
__device__ __forceinline__ void up2(u64 v, float& a, float& b) {
    asm("mov.b64 {%0, %1}, %2;" : "=f"(a), "=f"(b) : "l"(v));
}
__device__ __forceinline__ u64 fma2(u64 a, u64 b, u64 c) {
    u64 d;
    asm("fma.rn.f32x2 %0, %1, %2, %3;" : "=l"(d) : "l"(a), "l"(b), "l"(c));
    return d;
}
__device__ __forceinline__ u64 add2(u64 a, u64 b) {
    u64 d;
    asm("add.rn.f32x2 %0, %1, %2;" : "=l"(d) : "l"(a), "l"(b));
    return d;
}
// single-MUFU tanh (sm_75+): 1 instr, 16-cyc latency vs 4-instr/40-cyc ex2+rcp chain
__device__ __forceinline__ float tanha(float z) {
    float r;
    asm("tanh.approx.f32 %0, %1;" : "=f"(r) : "f"(z));
    return r;
}
__device__ __forceinline__ u64 tanh2a(u64 z) {
    float a, b;
    up2(z, a, b);
    return pk2(tanha(a), tanha(b));
}

// ---------- Fused producer/consumer kernel (R14 layout + tanh.approx) ----------
// Block = 4 pairs (8 batches), 128 threads. warps 0-1 consumers, warps 2-3 producers.
__global__ void __launch_bounds__(128, 4) kFused(
    const float* __restrict__ x,
    const float* __restrict__ h0in,
    const float* __restrict__ Wih0, const float* __restrict__ Whh0,
    const float* __restrict__ bih0, const float* __restrict__ bhh0,
    const float* __restrict__ Wih1, const float* __restrict__ Whh1,
    const float* __restrict__ bih1, const float* __restrict__ bhh1,
    const float* __restrict__ Wfc, const float* __restrict__ bfc,
    float* __restrict__ out)
{
    __shared__ __align__(16) u64 sU[4][4][16][17];   // [buf][ploc][i][t] padded
    __shared__ __align__(16) u64 swd[CC][HH];        // producer weights (dup f32x2)
    __shared__ u64 sb2[HH];                          // producer bias (dup f32x2)
    __shared__ __align__(16) ulonglong2 sh[2][2][17];// exchange [rw][s][i]={h0,h1}, padded

    int tid = threadIdx.x;
    int w = tid >> 5;
    int lane = tid & 31;
    int i = lane & 15;   // consumer: hidden unit; producer: t-slot
    int s = lane >> 4;   // pair slot

    // stage producer weights/bias (all threads help); no pre-scaling
    for (int k = tid; k < CC * HH; k += 128) {
        int c = k >> 4, ii = k & 15;
        float wv = Wih0[ii * CC + c];
        swd[c][ii] = pk2(wv, wv);
    }
    if (tid < HH) {
        float b = bih0[tid] + bhh0[tid];
        sb2[tid] = pk2(b, b);
    }
    __syncthreads();

    const bool is_prod = (w >= 2);
    int rw = is_prod ? (w - 2) : w;               // role-local warp index 0..1
    int ploc = rw * 2 + s;                        // 0..3
    int p = blockIdx.x * 4 + ploc;                // pair 0..2047
    int b0 = 2 * p, b1 = b0 + 1;

    if (is_prod) {
        // ================= producer: 12 double passes + 1 single =================
        const float* xa = x + (size_t)b0 * (CC * TT) + i;  // i = tl
        const float* xb = xa + CC * TT;
        for (int m = 0; m < 12; m++) {
            int j0 = 2 * m;
            int q0 = j0 & 3, q1 = (j0 + 1) & 3;
            if (j0 >= 4) {
                BAR_SYNC(5 + q0);  // consumers done with buf q0 (chunk j0-4)
                BAR_SYNC(5 + q1);
            }
            u64 u[32];
#pragma unroll
            for (int ii = 0; ii < 16; ii++) { u[ii] = sb2[ii]; u[16 + ii] = u[ii]; }
            const float* pa = xa + j0 * 16;
            const float* pb = xb + j0 * 16;
#pragma unroll 6
            for (int c = 0; c < CC; c++) {
                u64 xp0 = pk2(pa[c * TT], pb[c * TT]);
                u64 xp1 = pk2(pa[c * TT + 16], pb[c * TT + 16]);
                const ulonglong2* wp = (const ulonglong2*)&swd[c][0];
#pragma unroll
                for (int k8 = 0; k8 < 8; k8++) {
                    ulonglong2 w2 = wp[k8];
                    u[2 * k8]          = fma2(w2.x, xp0, u[2 * k8]);
                    u[2 * k8 + 1]      = fma2(w2.y, xp0, u[2 * k8 + 1]);
                    u[16 + 2 * k8]     = fma2(w2.x, xp1, u[16 + 2 * k8]);
                    u[16 + 2 * k8 + 1] = fma2(w2.y, xp1, u[16 + 2 * k8 + 1]);
                }
            }
            u64* d0 = &sU[q0][ploc][0][i];
            u64* d1 = &sU[q1][ploc][0][i];
#pragma unroll
            for (int ii = 0; ii < 16; ii++) {
                d0[ii * 17] = u[ii];
                d1[ii * 17] = u[16 + ii];
            }
            BAR_ARRIVE(1 + q0);  // buf q0 (chunk j0) full
            BAR_ARRIVE(1 + q1);  // buf q1 (chunk j0+1) full
        }
        {   // final single chunk j = 24 -> buf 0
            BAR_SYNC(5 + 0);
            u64 u[16];
#pragma unroll
            for (int ii = 0; ii < 16; ii++) u[ii] = sb2[ii];
            const float* pa = xa + 24 * 16;
            const float* pb = xb + 24 * 16;
#pragma unroll 6
            for (int c = 0; c < CC; c++) {
                u64 xp = pk2(pa[c * TT], pb[c * TT]);
                const ulonglong2* wp = (const ulonglong2*)&swd[c][0];
#pragma unroll
                for (int k8 = 0; k8 < 8; k8++) {
                    ulonglong2 w2 = wp[k8];
                    u[2 * k8] = fma2(w2.x, xp, u[2 * k8]);
                    u[2 * k8 + 1] = fma2(w2.y, xp, u[2 * k8 + 1]);
                }
            }
            u64* dst = &sU[0][ploc][0][i];
#pragma unroll
            for (int ii = 0; ii < 16; ii++) dst[ii * 17] = u[ii];
            BAR_ARRIVE(1 + 0);
        }
        return;
    }

    // ================= consumer =================
    u64 WH0[16], WI1[16], WH1[16];
#pragma unroll
    for (int j = 0; j < 16; j++) {
        float v0 = Whh0[i * 16 + j];
        float v1 = Wih1[i * 16 + j];
        float v2 = Whh1[i * 16 + j];
        WH0[j] = pk2(v0, v0);
        WI1[j] = pk2(v1, v1);
        WH1[j] = pk2(v2, v2);
    }
    float bf1 = bih1[i] + bhh1[i];
    u64 B1S = pk2(bf1, bf1);
    u64 h1ini = pk2(h0in[BB * HH + b0 * 16 + i], h0in[BB * HH + b1 * 16 + i]);
    u64 h0i = pk2(h0in[b0 * 16 + i], h0in[b1 * 16 + i]);

    ulonglong2* myh = &sh[rw][s][i];
    const ulonglong2* hrd = &sh[rw][s][0];
    const u64* ubase = &sU[0][ploc][i][0];
    const int bufstride = 4 * 16 * 17;  // u64 elements per buffer

    *myh = make_ulonglong2(h0i, h1ini);
    __syncwarp();

// one recurrence step: exchange holds {h0(m-1), h1(m-2)}; produces {h0(m), h1(m-1)}.
#define CSTEP(UVAL, OVRC)                                                          \
    {                                                                              \
        ulonglong2 qv;                                                             \
        u64 a0, a1, c0, c1, d0, d1;                                                \
        qv = hrd[0];  a0 = fma2(WH0[0], qv.x, (UVAL));                             \
                      c0 = fma2(WI1[0], qv.x, B1S);                                \
                      d0 = fma2(WH1[0], qv.y, 0ull);                               \
        qv = hrd[1];  a1 = fma2(WH0[1], qv.x, 0ull);                               \
                      c1 = fma2(WI1[1], qv.x, 0ull);                               \
                      d1 = fma2(WH1[1], qv.y, 0ull);                               \
        qv = hrd[2];  a0 = fma2(WH0[2], qv.x, a0);                                 \
                      c0 = fma2(WI1[2], qv.x, c0); d0 = fma2(WH1[2], qv.y, d0);    \
        qv = hrd[3];  a1 = fma2(WH0[3], qv.x, a1);                                 \
                      c1 = fma2(WI1[3], qv.x, c1); d1 = fma2(WH1[3], qv.y, d1);    \
        qv = hrd[4];  a0 = fma2(WH0[4], qv.x, a0);                                 \
                      c0 = fma2(WI1[4], qv.x, c0); d0 = fma2(WH1[4], qv.y, d0);    \
        qv = hrd[5];  a1 = fma2(WH0[5], qv.x, a1);                                 \
                      c1 = fma2(WI1[5], qv.x, c1); d1 = fma2(WH1[5], qv.y, d1);    \
        qv = hrd[6];  a0 = fma2(WH0[6], qv.x, a0);                                 \
                      c0 = fma2(WI1[6], qv.x, c0); d0 = fma2(WH1[6], qv.y, d0);    \
        qv = hrd[7];  a1 = fma2(WH0[7], qv.x, a1);                                 \
                      c1 = fma2(WI1[7], qv.x, c1); d1 = fma2(WH1[7], qv.y, d1);    \
        qv = hrd[8];  a0 = fma2(WH0[8], qv.x, a0);                                 \
                      c0 = fma2(WI1[8], qv.x, c0); d0 = fma2(WH1[8], qv.y, d0);    \
        qv = hrd[9];  a1 = fma2(WH0[9], qv.x, a1);                                 \
                      c1 = fma2(WI1[9], qv.x, c1); d1 = fma2(WH1[9], qv.y, d1);    \
        qv = hrd[10]; a0 = fma2(WH0[10], qv.x, a0);                                \
                      c0 = fma2(WI1[10], qv.x, c0); d0 = fma2(WH1[10], qv.y, d0);  \
        qv = hrd[11]; a1 = fma2(WH0[11], qv.x, a1);                                \
                      c1 = fma2(WI1[11], qv.x, c1); d1 = fma2(WH1[11], qv.y, d1);  \
        qv = hrd[12]; a0 = fma2(WH0[12], qv.x, a0);                                \
                      c0 = fma2(WI1[12], qv.x, c0); d0 = fma2(WH1[12], qv.y, d0);  \
        qv = hrd[13]; a1 = fma2(WH0[13], qv.x, a1);                                \
                      c1 = fma2(WI1[13], qv.x, c1); d1 = fma2(WH1[13], qv.y, d1);  \
        qv = hrd[14]; a0 = fma2(WH0[14], qv.x, a0);                                \
                      c0 = fma2(WI1[14], qv.x, c0); d0 = fma2(WH1[14], qv.y, d0);  \
        qv = hrd[15]; a1 = fma2(WH0[15], qv.x, a1);                                \
                      c1 = fma2(WI1[15], qv.x, c1); d1 = fma2(WH1[15], qv.y, d1);  \
        u64 h0n = tanh2a(add2(a0, a1));                                            \
        u64 h1n = tanh2a(add2(add2(c0, c1), add2(d0, d1)));                        \
        if (OVRC) h1n = h1ini;                                                     \
        *myh = make_ulonglong2(h0n, h1n);                                          \
    }

    for (int kk = 0; kk < NCH; kk++) {
        int q = kk & 3;
        BAR_SYNC(1 + q);  // wait: buf q holds chunk kk
        const u64* ur = ubase + q * bufstride;
        if (kk == 0) {
            {
                u64 uval = ur[0];
                CSTEP(uval, true);
            }
#pragma unroll
            for (int stp = 1; stp < 16; stp++) {
                u64 uval = ur[stp];
                CSTEP(uval, false);
            }
        } else {
#pragma unroll
            for (int stp = 0; stp < 16; stp++) {
                u64 uval = ur[stp];
                CSTEP(uval, false);
            }
        }
        BAR_ARRIVE(5 + q);  // buf q consumed
    }

    // exchange now holds {h0(399), h1(398)} — final step computes h1(399)
    {
        ulonglong2 qv;
        u64 c0, c1, d0, d1;
        qv = hrd[0];  c0 = fma2(WI1[0], qv.x, B1S);  d0 = fma2(WH1[0], qv.y, 0ull);
        qv = hrd[1];  c1 = fma2(WI1[1], qv.x, 0ull); d1 = fma2(WH1[1], qv.y, 0ull);
        qv = hrd[2];  c0 = fma2(WI1[2], qv.x, c0);   d0 = fma2(WH1[2], qv.y, d0);
        qv = hrd[3];  c1 = fma2(WI1[3], qv.x, c1);   d1 = fma2(WH1[3], qv.y, d1);
        qv = hrd[4];  c0 = fma2(WI1[4], qv.x, c0);   d0 = fma2(WH1[4], qv.y, d0);
        qv = hrd[5];  c1 = fma2(WI1[5], qv.x, c1);   d1 = fma2(WH1[5], qv.y, d1);
        qv = hrd[6];  c0 = fma2(WI1[6], qv.x, c0);   d0 = fma2(WH1[6], qv.y, d0);
        qv = hrd[7];  c1 = fma2(WI1[7], qv.x, c1);   d1 = fma2(WH1[7], qv.y, d1);
        qv = hrd[8];  c0 = fma2(WI1[8], qv.x, c0);   d0 = fma2(WH1[8], qv.y, d0);
        qv = hrd[9];  c1 = fma2(WI1[9], qv.x, c1);   d1 = fma2(WH1[9], qv.y, d1);
        qv = hrd[10]; c0 = fma2(WI1[10], qv.x, c0);  d0 = fma2(WH1[10], qv.y, d0);
        qv = hrd[11]; c1 = fma2(WI1[11], qv.x, c1);  d1 = fma2(WH1[11], qv.y, d1);
        qv = hrd[12]; c0 = fma2(WI1[12], qv.x, c0);  d0 = fma2(WH1[12], qv.y, d0);
        qv = hrd[13]; c1 = fma2(WI1[13], qv.x, c1);  d1 = fma2(WH1[13], qv.y, d1);
        qv = hrd[14]; c0 = fma2(WI1[14], qv.x, c0);  d0 = fma2(WH1[14], qv.y, d0);
        qv = hrd[15]; c1 = fma2(WI1[15], qv.x, c1);  d1 = fma2(WH1[15], qv.y, d1);
        u64 h1n = tanh2a(add2(add2(c0, c1), add2(d0, d1)));
        *myh = make_ulonglong2(0ull, h1n);
        __syncwarp();
    }
    // final FC (NC=2): out[b][c] = bfc[c] + sum_j Wfc[c][j] * h1(399)[j]
    if (i < 2) {
        float bfv = bfc[i];
        u64 acc = pk2(bfv, bfv);
#pragma unroll
        for (int j = 0; j < 16; j++) {
            float wv = Wfc[i * 16 + j];
            acc = fma2(pk2(wv, wv), hrd[j].y, acc);
        }
        float lo, hi;
        up2(acc, lo, hi);
        out[b0 * 2 + i] = lo;
        out[b1 * 2 + i] = hi;
    }
#undef CSTEP
}

extern "C" void kernel_launch(void* const* d_in, const int* in_sizes, int n_in,
                              void* d_out, int out_size) {
    const float* x    = (const float*)d_in[0];
    const float* h0   = (const float*)d_in[1];
    const float* Wih0 = (const float*)d_in[2];
    const float* Whh0 = (const float*)d_in[3];
    const float* bih0 = (const float*)d_in[4];
    const float* bhh0 = (const float*)d_in[5];
    const float* Wih1 = (const float*)d_in[6];
    const float* Whh1 = (const float*)d_in[7];
    const float* bih1 = (const float*)d_in[8];
    const float* bhh1 = (const float*)d_in[9];
    const float* Wfc  = (const float*)d_in[10];
    const float* bfc  = (const float*)d_in[11];
    float* out = (float*)d_out;

    kFused<<<512, 128>>>(x, h0, Wih0, Whh0, bih0, bhh0,
                         Wih1, Whh1, bih1, bhh1, Wfc, bfc, out);
}